// round 2
// baseline (speedup 1.0000x reference)
#include <cuda_runtime.h>
#include <cuda_bf16.h>
#include <stdint.h>

// Rules_67619965108887: fuzzy Larsen intersection with fixed (5,5,5) rule
// structure. out[row, r] = f(x[row,i0]) * f(x[row,5+i1]) * f(x[row,10+i2]),
// r = i0*25 + i1*5 + i2, f(v) = (v==0) ? 1 : v   (faithful to the
// jnp.where(rpu==0, 1, rpu) semantics, which also remaps selected zeros).
//
// Layout: warp-per-row, 8 rows per 256-thread block. Row's 15 floats staged
// in shared (coalesced global load, conflict-free broadcast LDS), each lane
// writes outputs r = lane, lane+32, lane+64, lane+96 -> fully coalesced STG.

static constexpr int F = 15;
static constexpr int R = 125;
static constexpr int ROWS_PER_BLOCK = 8;
static constexpr int THREADS = 256;

__global__ __launch_bounds__(THREADS)
void Rules_67619965108887_kernel(const float* __restrict__ x,
                                 float* __restrict__ out,
                                 int n_rows) {
    __shared__ float sx[ROWS_PER_BLOCK][F + 1];  // +1 pad: rows start on distinct banks

    const int tid = threadIdx.x;
    const int block_row0 = blockIdx.x * ROWS_PER_BLOCK;

    // Stage ROWS_PER_BLOCK * F = 120 floats, coalesced. Apply f(v)=(v==0?1:v)
    // once here so the product loop is pure multiplies.
    if (tid < ROWS_PER_BLOCK * F) {
        const long long gidx = (long long)block_row0 * F + tid;
        if (gidx < (long long)n_rows * F) {
            float v = x[gidx];
            sx[tid / F][tid % F] = (v == 0.0f) ? 1.0f : v;
        }
    }
    __syncthreads();

    const int w    = tid >> 5;
    const int lane = tid & 31;
    const int row  = block_row0 + w;
    if (row >= n_rows) return;

    const float* __restrict__ xr = sx[w];
    float* __restrict__ orow = out + (long long)row * R;

#pragma unroll
    for (int t = 0; t < 4; t++) {
        const int r = lane + 32 * t;
        if (r < R) {
            const int i0  = r / 25;
            const int rem = r - i0 * 25;
            const int i1  = rem / 5;
            const int i2  = rem - i1 * 5;
            orow[r] = xr[i0] * xr[5 + i1] * xr[10 + i2];
        }
    }
}

extern "C" void kernel_launch(void* const* d_in, const int* in_sizes, int n_in,
                              void* d_out, int out_size) {
    // metadata order: x (float32, B*S*F), active_rules (float32, 125*15), epoch (int)
    const float* x = (const float*)d_in[0];
    float* out = (float*)d_out;

    const int n_rows = in_sizes[0] / F;  // B*S = 32768
    const int grid = (n_rows + ROWS_PER_BLOCK - 1) / ROWS_PER_BLOCK;

    Rules_67619965108887_kernel<<<grid, THREADS>>>(x, out, n_rows);
}

// round 3
// speedup vs baseline: 1.0179x; 1.0179x over previous
#include <cuda_runtime.h>
#include <cuda_bf16.h>
#include <stdint.h>

// Rules_67619965108887: out[row, r] = f(x[i0])*f(x[5+i1])*f(x[10+i2]),
// r = i0*25+i1*5+i2, f(v)= (v==0)?1:v.
//
// Strategy (issue-bound per R2 ncu: issue 66.7%, DRAM 2.7%):
//   1. stage row inputs (f-fixed) in smem, coalesced
//   2. per row build p[25] = f(a)*f(b) and c[5] tables (factor the outer product)
//   3. group phase: item i = row*25+j emits 5 outputs p[j]*c[0..4] at smem
//      offset 5i (identity: row*125 + j*5 == 5*i) -> almost no index math
//   4. flush smem -> gmem with coalesced float4 stores (block span 16000B,
//      16B-aligned for ROWS=32)

static constexpr int F = 15;
static constexpr int R = 125;
static constexpr int ROWS = 32;
static constexpr int THREADS = 256;

__global__ __launch_bounds__(THREADS)
void Rules_67619965108887_kernel(const float* __restrict__ x,
                                 float* __restrict__ out,
                                 int n_rows) {
    __shared__ float sx[ROWS][16];     // f-fixed inputs, padded row stride
    __shared__ float tp[ROWS][32];     // cols 0..24: p-table, cols 25..29: c
    __shared__ float so[ROWS * R];     // staged outputs (4000 floats)

    const int tid = threadIdx.x;
    const int row0 = blockIdx.x * ROWS;
    const int nrow = min(ROWS, n_rows - row0);

    // ---- stage inputs (coalesced LDG), apply f(v) = (v==0)?1:v once ----
    const int nstage = nrow * F;
    for (int i = tid; i < nstage; i += THREADS) {
        float v = x[(long long)row0 * F + i];
        sx[i / F][i % F] = (v == 0.0f) ? 1.0f : v;
    }
    __syncthreads();

    // ---- build per-row tables: 25 pairwise products + 5 c copies ----
    const int nbuild = nrow * 30;
    for (int i = tid; i < nbuild; i += THREADS) {
        const int row = i / 30;
        const int j = i - row * 30;
        float v;
        if (j < 25) {
            v = sx[row][j / 5] * sx[row][5 + (j - (j / 5) * 5)];
        } else {
            v = sx[row][j - 15];  // 10 + (j - 25)
        }
        tp[row][j] = v;
    }
    __syncthreads();

    // ---- group phase: each item emits 5 outputs, offset = 5*i ----
    const int ngroup = nrow * 25;
    for (int i = tid; i < ngroup; i += THREADS) {
        const int row = i / 25;
        const float p = tp[row][i - row * 25];
        const float* __restrict__ c = &tp[row][25];
        float* __restrict__ o = &so[5 * i];
        o[0] = p * c[0];
        o[1] = p * c[1];
        o[2] = p * c[2];
        o[3] = p * c[3];
        o[4] = p * c[4];
    }
    __syncthreads();

    // ---- flush: coalesced float4 stores ----
    const int ntot = nrow * R;
    const int nf4 = ntot >> 2;
    float4* __restrict__ o4 = (float4*)(out + (long long)row0 * R);
    const float4* __restrict__ s4 = (const float4*)so;
    for (int v = tid; v < nf4; v += THREADS) {
        o4[v] = s4[v];
    }
    // scalar tail (only for partial last block with nrow % 4 != 0)
    for (int i = (nf4 << 2) + tid; i < ntot; i += THREADS) {
        out[(long long)row0 * R + i] = so[i];
    }
}

extern "C" void kernel_launch(void* const* d_in, const int* in_sizes, int n_in,
                              void* d_out, int out_size) {
    const float* x = (const float*)d_in[0];
    float* out = (float*)d_out;

    const int n_rows = in_sizes[0] / F;  // B*S = 32768
    const int grid = (n_rows + ROWS - 1) / ROWS;

    Rules_67619965108887_kernel<<<grid, THREADS>>>(x, out, n_rows);
}